// round 17
// baseline (speedup 1.0000x reference)
#include <cuda_runtime.h>
#include <cuda.h>

// out[b,pi,pj,h,w] = leaky_relu( (1/32) * sum_c x1[b,c,h,w] *
//                    x2_pad[b,c, h+2*pi-20, w+2*pj-20], 0.1 )
// B=4, C=32, H=32, W=1024, PATCH=21, DIL=2, PAD=20.
// 3D-TMA staging (OOB zero-fill), triple-buffered (prefetch distance 2),
// LPT launch order, validity skip, sync-free stage loop, full channel unroll.

#define WT      128
#define SLICE   168
#define CPH     4
#define NBUF    3
#define BUF_FLOATS (CPH * SLICE)          // 672
#define TMA_BYTES  (SLICE * CPH * 4)      // 2688

__device__ __forceinline__ unsigned long long ffma2(unsigned long long a,
                                                    unsigned long long b,
                                                    unsigned long long c) {
    unsigned long long d;
    asm("fma.rn.f32x2 %0, %1, %2, %3;" : "=l"(d) : "l"(a), "l"(b), "l"(c));
    return d;
}

__device__ __forceinline__ void mbar_init(unsigned mb) {
    asm volatile("mbarrier.init.shared.b64 [%0], 1;" :: "r"(mb) : "memory");
}
__device__ __forceinline__ void mbar_expect(unsigned mb, unsigned bytes) {
    asm volatile("mbarrier.arrive.expect_tx.shared.b64 _, [%0], %1;"
                 :: "r"(mb), "r"(bytes) : "memory");
}
__device__ __forceinline__ void tma3d(unsigned dst, const CUtensorMap* m,
                                      int c0, int c1, int c2, unsigned mb) {
    asm volatile(
        "cp.async.bulk.tensor.3d.shared::cta.global.tile.mbarrier::complete_tx::bytes "
        "[%0], [%1, {%2, %3, %4}], [%5];"
        :: "r"(dst), "l"(m), "r"(c0), "r"(c1), "r"(c2), "r"(mb) : "memory");
}
__device__ __forceinline__ void mbar_wait(unsigned mb, unsigned phase) {
    asm volatile(
        "{\n\t"
        ".reg .pred P;\n\t"
        "LAB_WAIT_%=:\n\t"
        "mbarrier.try_wait.parity.acquire.cta.shared::cta.b64 P, [%0], %1, 0x989680;\n\t"
        "@P bra.uni LAB_DONE_%=;\n\t"
        "bra.uni LAB_WAIT_%=;\n\t"
        "LAB_DONE_%=:\n\t"
        "}"
        :: "r"(mb), "r"(phase) : "memory");
}

extern __shared__ float smem[];

__global__ void __launch_bounds__(128, 4)
corr_kernel(const float* __restrict__ x1, const float* __restrict__ x2,
            float* __restrict__ out, const __grid_constant__ CUtensorMap tmap)
{
    const int w0   = blockIdx.x * WT;
    // LPT order: y walks h center-out (descending valid-pi count V(h))
    const int yy   = blockIdx.y;
    const int h    = (yy & 1) ? (16 + (yy >> 1)) : (15 - (yy >> 1));
    const int b    = blockIdx.z;
    const int tid  = threadIdx.x;
    const int wid  = tid >> 5;          // 4 warps
    const int lane = tid & 31;
    const int g    = lane >> 1;         // 16 w-groups of 8 w's
    const int half = lane & 1;          // 0: pj 0..10, 1: pj 10..20

    float* x1s = smem;                                       // [32][WT]
    float* x2b = smem + 32 * WT + wid * (NBUF * BUF_FLOATS);

    const unsigned smem_b  = (unsigned)__cvta_generic_to_shared(smem);
    const unsigned mb_base = smem_b +
        (unsigned)(32 * WT + 4 * NBUF * BUF_FLOATS) * 4u + (unsigned)wid * 24u;
    // 3 mbarriers per warp (one per buffer)

    // ---- stage x1 tile: 32 channels x WT floats ----
    for (int f = tid; f < 32 * (WT / 4); f += 128) {
        const int c = f >> 5;
        const int j = f & 31;
        reinterpret_cast<float4*>(x1s)[f] = *reinterpret_cast<const float4*>(
            x1 + ((size_t)(b * 32 + c) * 32 + h) * 1024 + w0 + 4 * j);
    }
    __syncthreads();

    if (lane == 0) {
        mbar_init(mb_base);
        mbar_init(mb_base + 8);
        mbar_init(mb_base + 16);
    }
    __syncwarp();   // mbarrier init visible warp-wide

    // valid pi range for this h: h2 = h + 2*pi - 20 in [0,32)
    const int pi_lo = (h >= 21) ? 0 : ((21 - h) >> 1);
    const int pi_hi = ((51 - h) >> 1) < 20 ? ((51 - h) >> 1) : 20;
    const int kmax = (20 - wid) >> 2;
    const int k0   = (pi_lo > wid) ? ((pi_lo - wid + 3) >> 2) : 0;
    const int k1   = (pi_hi - wid) >> 2;
    const int nval = k1 - k0 + 1;               // >= 2 always
    const int total = nval * 8;                 // >= 16

    // acc[p][q]: pj = p + 10*half, w-pair q of this lane's 8 w's
    unsigned long long acc[11][4];
    #pragma unroll
    for (int p = 0; p < 11; p++)
        #pragma unroll
        for (int q = 0; q < 4; q++) acc[p][q] = 0ull;

    const float* x1base = x1s + 8 * g;
    const float sp = 0.03125f;    // 1/32
    const float sn = 0.003125f;   // 0.1/32

    // producer: stage s -> pi = wid + (k0 + (s>>3))*4, phase = s&7
    const int h2_0 = h + 2 * (wid + (k0 << 2)) - 20;   // h2 at k=k0 (valid)
    const int bc0  = b * 32;                           // dim2 base (b,c=0)
    const int wtm  = w0 - 20;                          // dim0 coord (may be <0)
    const unsigned dstb = smem_b +
        (unsigned)(32 * WT + wid * (NBUF * BUF_FLOATS)) * 4u;

    auto do_stage = [&](int s) {
        if (lane == 0) {
            const int bi = s - 3 * (s / 3);            // s % 3
            const unsigned mb = mb_base + (unsigned)bi * 8u;
            mbar_expect(mb, TMA_BYTES);
            tma3d(dstb + (unsigned)(bi * (BUF_FLOATS * 4)), &tmap,
                  wtm, h2_0 + ((s >> 3) << 3), bc0 + ((s & 7) << 2), mb);
        }
    };

    do_stage(0);
    do_stage(1);

    unsigned pbits = 0;   // per-buffer consumer parity bits

    for (int s = 0; s < total; s++) {
        if (s + 2 < total) do_stage(s + 2);

        const int bi = s - 3 * (s / 3);                // s % 3
        mbar_wait(mb_base + (unsigned)bi * 8u, (pbits >> bi) & 1u);
        pbits ^= (1u << bi);

        // ---- compute stage s: 4 channels ----
        const float* buf = x2b + bi * BUF_FLOATS;
        const int ph = s & 7;
        const float* x1p = x1base + ph * (CPH * WT);
        const float* xwp = buf + 8 * g + 20 * half;

        #pragma unroll
        for (int c = 0; c < CPH; c++) {
            const float* x1row = x1p + c * WT;
            const ulonglong2 A0 = *reinterpret_cast<const ulonglong2*>(x1row);
            const ulonglong2 A1 = *reinterpret_cast<const ulonglong2*>(x1row + 4);
            const unsigned long long a[4] = {A0.x, A0.y, A1.x, A1.y};

            ulonglong2 X[7];
            const float* bp = xwp + c * SLICE;
            #pragma unroll
            for (int j = 0; j < 7; j++)
                X[j] = *reinterpret_cast<const ulonglong2*>(bp + 4 * j);

            #pragma unroll
            for (int p = 0; p < 11; p++) {
                #pragma unroll
                for (int q = 0; q < 4; q++) {
                    const int k = p + q;                       // 0..13
                    const unsigned long long pk = (k & 1) ? X[k >> 1].y
                                                          : X[k >> 1].x;
                    acc[p][q] = ffma2(a[q], pk, acc[p][q]);
                }
            }
        }

        // ---- per-pi epilogue after last phase ----
        if ((s & 7) == 7) {
            const int pi = wid + ((k0 + (s >> 3)) << 2);
            #pragma unroll
            for (int p = 0; p < 11; p++) {
                if (!(half == 1 && p == 0)) {      // pj=10 dup by half A
                    const int pj = half ? (p + 10) : p;
                    float* op = out +
                        (((size_t)b * 441 + pi * 21 + pj) * 32 + h) * 1024 +
                        w0 + 8 * g;
                    float v[8];
                    #pragma unroll
                    for (int q = 0; q < 4; q++) {
                        float2 fv = *reinterpret_cast<float2*>(&acc[p][q]);
                        v[2 * q]     = fv.x * ((fv.x < 0.f) ? sn : sp);
                        v[2 * q + 1] = fv.y * ((fv.y < 0.f) ? sn : sp);
                    }
                    *reinterpret_cast<float4*>(op) =
                        make_float4(v[0], v[1], v[2], v[3]);
                    *reinterpret_cast<float4*>(op + 4) =
                        make_float4(v[4], v[5], v[6], v[7]);
                }
                #pragma unroll
                for (int q = 0; q < 4; q++) acc[p][q] = 0ull;
            }
        }
    }

    // ---- zero-store epilogue for out-of-range pi (h2 invalid -> out = 0) ----
    {
        const float4 z = make_float4(0.f, 0.f, 0.f, 0.f);
        for (int k = 0; k <= kmax; k++) {
            if (k >= k0 && k <= k1) continue;
            const int pi = wid + (k << 2);
            #pragma unroll
            for (int p = 0; p < 11; p++) {
                if (half == 1 && p == 0) continue;
                const int pj = half ? (p + 10) : p;
                float* op = out +
                    (((size_t)b * 441 + pi * 21 + pj) * 32 + h) * 1024 +
                    w0 + 8 * g;
                *reinterpret_cast<float4*>(op)     = z;
                *reinterpret_cast<float4*>(op + 4) = z;
            }
        }
    }
}

typedef CUresult (*TMEncodeFn)(
    CUtensorMap*, CUtensorMapDataType, cuuint32_t, void*,
    const cuuint64_t*, const cuuint64_t*, const cuuint32_t*, const cuuint32_t*,
    CUtensorMapInterleave, CUtensorMapSwizzle, CUtensorMapL2promotion,
    CUtensorMapFloatOOBfill);

extern "C" void kernel_launch(void* const* d_in, const int* in_sizes, int n_in,
                              void* d_out, int out_size) {
    const float* x1 = (const float*)d_in[0];
    const float* x2 = (const float*)d_in[1];
    float* out = (float*)d_out;

    // 3D tensor map for x2 viewed as [W=1024, H=32, B*C=128] f32.
    void* fn = nullptr;
    cudaDriverEntryPointQueryResult qr;
    cudaGetDriverEntryPoint("cuTensorMapEncodeTiled", &fn,
                            cudaEnableDefault, &qr);
    CUtensorMap tmap;
    cuuint64_t dims[3]    = {1024, 32, 128};
    cuuint64_t strides[2] = {1024ull * 4, 32ull * 1024 * 4};
    cuuint32_t box[3]     = {SLICE, 1, CPH};
    cuuint32_t es[3]      = {1, 1, 1};
    ((TMEncodeFn)fn)(&tmap, CU_TENSOR_MAP_DATA_TYPE_FLOAT32, 3, (void*)x2,
                     dims, strides, box, es,
                     CU_TENSOR_MAP_INTERLEAVE_NONE,
                     CU_TENSOR_MAP_SWIZZLE_NONE,
                     CU_TENSOR_MAP_L2_PROMOTION_L2_128B,
                     CU_TENSOR_MAP_FLOAT_OOB_FILL_NONE);

    // x1 tile + 4 warps * 3 buffers * 672 floats + 12 mbarriers
    const size_t smem_bytes =
        (size_t)(32 * WT + 4 * NBUF * BUF_FLOATS) * sizeof(float) + 96;  // 48736 B
    cudaFuncSetAttribute(corr_kernel,
                         cudaFuncAttributeMaxDynamicSharedMemorySize,
                         (int)smem_bytes);

    dim3 grid(1024 / WT, 32, 4);   // (w-tiles, h-order, B)
    corr_kernel<<<grid, 128, smem_bytes>>>(x1, x2, out, tmap);
}